// round 4
// baseline (speedup 1.0000x reference)
#include <cuda_runtime.h>
#include <cstdint>
#include <cstddef>

#define BATCH    64
#define SEQ      2048
#define INPUT    8
#define HIDDEN   512
#define NUM_SEEDS 4
#define DD       12
#define OUTK     10
#define ALPHA_F  0.1f
#define K1_F     (0.1f * (500.0f/512.0f))
#define CHAINS_PER_BLOCK 2

// ---------------- scratch (static __device__ — no allocation) ----------------
__device__ float g_m0[NUM_SEEDS][HIDDEN];
__device__ float g_m1[NUM_SEEDS][HIDDEN];
__device__ float g_n0[NUM_SEEDS][HIDDEN];
__device__ float g_n1[NUM_SEEDS][HIDDEN];
__device__ float g_I [NUM_SEEDS][HIDDEN][INPUT];

// fast tanh: 1 - 2/(exp(2x)+1). Error ~1e-6; exact saturation.
__device__ __forceinline__ float fast_tanh(float x) {
    float e = __expf(2.0f * x);
    return 1.0f - __fdividef(2.0f, e + 1.0f);
}

// group-local named barrier (decouples the two chains sharing a block)
__device__ __forceinline__ void group_bar(int grp) {
    asm volatile("bar.sync %0, 128;" :: "r"(grp + 1) : "memory");
}

// ---------------- kernel 1: combined mixture -> m, n, I ----------------
__global__ void setup_kernel(const float* __restrict__ means,
                             const float* __restrict__ L,
                             const float* __restrict__ mw,
                             const float* __restrict__ seeds) {
    __shared__ float Lc[DD][DD];
    __shared__ float mc[DD];
    int tid = threadIdx.x;

    float w0 = fmaxf(mw[0], 1e-6f);
    float w1 = fmaxf(mw[1], 1e-6f);
    float inv = 1.0f / (w0 + w1);
    w0 *= inv; w1 *= inv;

    if (tid < DD * DD) {
        int d = tid / DD, e = tid - d * DD;
        float a = L[d * DD + e];
        float c = L[DD * DD + d * DD + e];
        float v = 0.0f;
        if (e < d) {
            v = w0 * a + w1 * c;
        } else if (e == d) {
            v = w0 * (fabsf(a - 1e-12f) + 1e-12f)
              + w1 * (fabsf(c - 1e-12f) + 1e-12f);
        }
        Lc[d][e] = v;
    }
    if (tid < DD) mc[tid] = w0 * means[tid] + w1 * means[DD + tid];
    __syncthreads();

    int g = blockIdx.x * blockDim.x + tid;      // 0..2047 = s*512 + h
    int s = g >> 9, h = g & 511;

    float sd[DD];
    #pragma unroll
    for (int e = 0; e < DD; e++) sd[e] = seeds[(size_t)g * DD + e];

    float comb[DD];
    #pragma unroll
    for (int d = 0; d < DD; d++) {
        float v = mc[d];
        for (int e = 0; e <= d; e++) v = fmaf(Lc[d][e], sd[e], v);
        comb[d] = v;
    }
    g_m0[s][h] = comb[0];
    g_m1[s][h] = comb[1];
    g_n0[s][h] = comb[2];
    g_n1[s][h] = comb[3];
    #pragma unroll
    for (int i = 0; i < INPUT; i++) g_I[s][h][i] = comb[4 + i];
}

// ---------------- kernel 2: output channels 2..9 (x-only, via pinv@span == I) ----
// out_t[2+i] = 0.9*out_{t-1}[2+i] + 0.1*x_t[i].  Independent of the RNN.
__global__ __launch_bounds__(32) void xout_kernel(const float* __restrict__ x,
                                                  float* __restrict__ out) {
    const int b = blockIdx.x;
    const int lane = threadIdx.x;
    if (lane >= INPUT) return;

    const float* src = x + (size_t)b * SEQ * INPUT + lane;
    float* ob = out + (size_t)b * SEQ * OUTK + 2 + lane;

    float acc = 0.0f;
    #pragma unroll 8
    for (int t = 0; t < SEQ; t++) {
        acc = fmaf(0.9f, acc, ALPHA_F * src[(size_t)t * INPUT]);
        ob[(size_t)t * OUTK] = acc;
    }
}

// ---------------- kernel 3: the sequential RNN scan ----------------
// 2 independent batches per block (warps 0-3 / 4-7), so each SMSP carries two
// independent chains and their stalls interleave. Group-local named barriers
// keep the chains decoupled. Inner loop identical to the proven R3 version.
__global__ __launch_bounds__(128 * CHAINS_PER_BLOCK, 1)
void rnn_kernel(const float* __restrict__ x,
                const int* __restrict__ cur_seeds,
                float* __restrict__ out) {
    const int grp  = threadIdx.x >> 7;            // chain within block
    const int tid  = threadIdx.x & 127;           // thread within chain
    const int b    = blockIdx.x * CHAINS_PER_BLOCK + grp;
    const int wid  = tid >> 5, lane = tid & 31;
    const int s    = cur_seeds[b];
    const int h0   = tid * 4;

    const float4 M0 = *(const float4*)&g_m0[s][h0];
    const float4 M1 = *(const float4*)&g_m1[s][h0];
    const float4 N0 = *(const float4*)&g_n0[s][h0];
    const float4 N1 = *(const float4*)&g_n1[s][h0];
    float Iw[4][INPUT];
    #pragma unroll
    for (int c = 0; c < 4; c++) {
        float4 ia = *(const float4*)&g_I[s][h0 + c][0];
        float4 ib = *(const float4*)&g_I[s][h0 + c][4];
        Iw[c][0] = ia.x; Iw[c][1] = ia.y; Iw[c][2] = ia.z; Iw[c][3] = ia.w;
        Iw[c][4] = ib.x; Iw[c][5] = ib.y; Iw[c][6] = ib.z; Iw[c][7] = ib.w;
    }

    const float* xb = x + (size_t)b * SEQ * INPUT;
    float2* ob01 = (float2*)(out + (size_t)b * SEQ * OUTK);   // channels 0,1

    __shared__ __align__(16) float sp[CHAINS_PER_BLOCK][2][2][4]; // [grp][parity][r][warp]

    float h[4] = {0.f, 0.f, 0.f, 0.f};
    float oa = 0.0f, obv = 0.0f;                  // out channel 0/1 scans (tid 0)
    float4 xA = *(const float4*)(xb + 0);
    float4 xB = *(const float4*)(xb + 4);

    for (int t = 0; t < SEQ; t++) {
        // prefetch next x row (broadcast loads, off critical path)
        int tn = (t + 1 < SEQ) ? t + 1 : t;
        float4 xAn = *(const float4*)(xb + (size_t)tn * INPUT);
        float4 xBn = *(const float4*)(xb + (size_t)tn * INPUT + 4);

        float th0 = fast_tanh(h[0]);
        float th1 = fast_tanh(h[1]);
        float th2 = fast_tanh(h[2]);
        float th3 = fast_tanh(h[3]);

        float q0 = fmaf(N0.x, th0, N0.y * th1) + fmaf(N0.z, th2, N0.w * th3);
        float q1 = fmaf(N1.x, th0, N1.y * th1) + fmaf(N1.z, th2, N1.w * th3);

        #pragma unroll
        for (int off = 16; off > 0; off >>= 1) {
            q0 += __shfl_xor_sync(0xffffffffu, q0, off);
            q1 += __shfl_xor_sync(0xffffffffu, q1, off);
        }

        // Ix_t (independent of h — issues under the shuffle-chain latency)
        float aix[4];
        #pragma unroll
        for (int c = 0; c < 4; c++) {
            float v =          Iw[c][0] * xA.x;
            v = fmaf(Iw[c][1], xA.y, v);
            v = fmaf(Iw[c][2], xA.z, v);
            v = fmaf(Iw[c][3], xA.w, v);
            v = fmaf(Iw[c][4], xB.x, v);
            v = fmaf(Iw[c][5], xB.y, v);
            v = fmaf(Iw[c][6], xB.z, v);
            v = fmaf(Iw[c][7], xB.w, v);
            aix[c] = ALPHA_F * v;
        }

        int par = t & 1;
        if (lane == 0) { sp[grp][par][0][wid] = q0; sp[grp][par][1][wid] = q1; }
        group_bar(grp);
        float4 P0 = *(const float4*)&sp[grp][par][0][0];
        float4 P1 = *(const float4*)&sp[grp][par][1][0];
        float p0 = (P0.x + P0.y) + (P0.z + P0.w);
        float p1 = (P1.x + P1.y) + (P1.z + P1.w);

        h[0] = fmaf(0.9f, h[0], fmaf(K1_F, fmaf(M0.x, p0, M1.x * p1), aix[0]));
        h[1] = fmaf(0.9f, h[1], fmaf(K1_F, fmaf(M0.y, p0, M1.y * p1), aix[1]));
        h[2] = fmaf(0.9f, h[2], fmaf(K1_F, fmaf(M0.z, p0, M1.z * p1), aix[2]));
        h[3] = fmaf(0.9f, h[3], fmaf(K1_F, fmaf(M0.w, p0, M1.w * p1), aix[3]));

        // out channels 0,1: leaky scan of the rank coefficients (off h-critical-path)
        if (tid == 0) {
            oa  = fmaf(0.9f, oa,  K1_F * p0);
            obv = fmaf(0.9f, obv, K1_F * p1);
            ob01[(size_t)t * (OUTK / 2)] = make_float2(oa, obv);
        }

        xA = xAn; xB = xBn;
    }
}

// ---------------- launch ----------------
extern "C" void kernel_launch(void* const* d_in, const int* in_sizes, int n_in,
                              void* d_out, int out_size) {
    const float* x     = (const float*)d_in[0];   // (64,2048,8)
    const float* means = (const float*)d_in[1];   // (2,12)
    const float* L     = (const float*)d_in[2];   // (2,12,12)
    const float* mw    = (const float*)d_in[3];   // (2,)
    const float* seeds = (const float*)d_in[4];   // (4,512,12)
    const int*   cs    = (const int*)d_in[5];     // (64,)
    float* out = (float*)d_out;                   // (64,2048,10)

    setup_kernel<<<8, 256>>>(means, L, mw, seeds);
    xout_kernel<<<BATCH, 32>>>(x, out);
    rnn_kernel<<<BATCH / CHAINS_PER_BLOCK, 128 * CHAINS_PER_BLOCK>>>(x, cs, out);
}

// round 5
// speedup vs baseline: 1.4579x; 1.4579x over previous
#include <cuda_runtime.h>
#include <cstdint>
#include <cstddef>

#define BATCH    64
#define SEQ      2048
#define INPUT    8
#define HIDDEN   512
#define NUM_SEEDS 4
#define DD       12
#define OUTK     10
#define ALPHA_F  0.1f
#define K1_F     (0.1f * (500.0f/512.0f))

// ---------------- scratch (static __device__ — no allocation) ----------------
__device__ float g_m0[NUM_SEEDS][HIDDEN];
__device__ float g_m1[NUM_SEEDS][HIDDEN];
__device__ float g_n0[NUM_SEEDS][HIDDEN];
__device__ float g_n1[NUM_SEEDS][HIDDEN];
__device__ float g_I [NUM_SEEDS][HIDDEN][INPUT];

// native tanh (MUFU.TANH, sm_75+): 1 MUFU op, ~16cyc; rel err ~2^-11.
__device__ __forceinline__ float fast_tanh(float x) {
    float r;
    asm("tanh.approx.f32 %0, %1;" : "=f"(r) : "f"(x));
    return r;
}

// ---------------- kernel 1: combined mixture -> m, n, I ----------------
__global__ void setup_kernel(const float* __restrict__ means,
                             const float* __restrict__ L,
                             const float* __restrict__ mw,
                             const float* __restrict__ seeds) {
    __shared__ float Lc[DD][DD];
    __shared__ float mc[DD];
    int tid = threadIdx.x;

    float w0 = fmaxf(mw[0], 1e-6f);
    float w1 = fmaxf(mw[1], 1e-6f);
    float inv = 1.0f / (w0 + w1);
    w0 *= inv; w1 *= inv;

    if (tid < DD * DD) {
        int d = tid / DD, e = tid - d * DD;
        float a = L[d * DD + e];
        float c = L[DD * DD + d * DD + e];
        float v = 0.0f;
        if (e < d) {
            v = w0 * a + w1 * c;
        } else if (e == d) {
            v = w0 * (fabsf(a - 1e-12f) + 1e-12f)
              + w1 * (fabsf(c - 1e-12f) + 1e-12f);
        }
        Lc[d][e] = v;
    }
    if (tid < DD) mc[tid] = w0 * means[tid] + w1 * means[DD + tid];
    __syncthreads();

    int g = blockIdx.x * blockDim.x + tid;      // 0..2047 = s*512 + h
    int s = g >> 9, h = g & 511;

    float sd[DD];
    #pragma unroll
    for (int e = 0; e < DD; e++) sd[e] = seeds[(size_t)g * DD + e];

    float comb[DD];
    #pragma unroll
    for (int d = 0; d < DD; d++) {
        float v = mc[d];
        for (int e = 0; e <= d; e++) v = fmaf(Lc[d][e], sd[e], v);
        comb[d] = v;
    }
    g_m0[s][h] = comb[0];
    g_m1[s][h] = comb[1];
    g_n0[s][h] = comb[2];
    g_n1[s][h] = comb[3];
    #pragma unroll
    for (int i = 0; i < INPUT; i++) g_I[s][h][i] = comb[4 + i];
}

// ---------------- kernel 2: output channels 2..9 (x-only, via pinv@span == I) ----
// out_t[2+i] = 0.9*out_{t-1}[2+i] + 0.1*x_t[i].  Independent of the RNN.
__global__ __launch_bounds__(32) void xout_kernel(const float* __restrict__ x,
                                                  float* __restrict__ out) {
    const int b = blockIdx.x;
    const int lane = threadIdx.x;
    if (lane >= INPUT) return;

    const float* src = x + (size_t)b * SEQ * INPUT + lane;
    float* ob = out + (size_t)b * SEQ * OUTK + 2 + lane;

    float acc = 0.0f;
    #pragma unroll 8
    for (int t = 0; t < SEQ; t++) {
        acc = fmaf(0.9f, acc, ALPHA_F * src[(size_t)t * INPUT]);
        ob[(size_t)t * OUTK] = acc;
    }
}

// ---------------- kernel 3: the sequential RNN scan (R3 structure) ----------------
// 1 block per batch, 128 threads, 4 hidden units per thread (contiguous).
// Per step: th=tanh(h); q_r = n_r . th (5-round warp shuffle + smem cross-warp);
// h = 0.9h + K1*(m0 p0 + m1 p1) + 0.1*(I x_t).
// tid 0 additionally runs the rank-coefficient leaky scans and writes out[...,0:2].
__global__ __launch_bounds__(128, 1) void rnn_kernel(const float* __restrict__ x,
                                                     const int* __restrict__ cur_seeds,
                                                     float* __restrict__ out) {
    const int b = blockIdx.x;
    const int tid = threadIdx.x;
    const int wid = tid >> 5, lane = tid & 31;
    const int s = cur_seeds[b];
    const int h0 = tid * 4;

    const float4 M0 = *(const float4*)&g_m0[s][h0];
    const float4 M1 = *(const float4*)&g_m1[s][h0];
    const float4 N0 = *(const float4*)&g_n0[s][h0];
    const float4 N1 = *(const float4*)&g_n1[s][h0];
    float Iw[4][INPUT];
    #pragma unroll
    for (int c = 0; c < 4; c++) {
        float4 ia = *(const float4*)&g_I[s][h0 + c][0];
        float4 ib = *(const float4*)&g_I[s][h0 + c][4];
        Iw[c][0] = ia.x; Iw[c][1] = ia.y; Iw[c][2] = ia.z; Iw[c][3] = ia.w;
        Iw[c][4] = ib.x; Iw[c][5] = ib.y; Iw[c][6] = ib.z; Iw[c][7] = ib.w;
    }

    const float* xb = x + (size_t)b * SEQ * INPUT;
    float2* ob01 = (float2*)(out + (size_t)b * SEQ * OUTK);   // channels 0,1

    __shared__ __align__(16) float sp[2][2][4];   // [parity][r][warp]

    float h[4] = {0.f, 0.f, 0.f, 0.f};
    float oa = 0.0f, obv = 0.0f;                  // out channel 0/1 scans (tid 0)
    float4 xA = *(const float4*)(xb + 0);
    float4 xB = *(const float4*)(xb + 4);

    for (int t = 0; t < SEQ; t++) {
        // prefetch next x row (broadcast loads, off critical path)
        int tn = (t + 1 < SEQ) ? t + 1 : t;
        float4 xAn = *(const float4*)(xb + (size_t)tn * INPUT);
        float4 xBn = *(const float4*)(xb + (size_t)tn * INPUT + 4);

        float th0 = fast_tanh(h[0]);
        float th1 = fast_tanh(h[1]);
        float th2 = fast_tanh(h[2]);
        float th3 = fast_tanh(h[3]);

        float q0 = fmaf(N0.x, th0, N0.y * th1) + fmaf(N0.z, th2, N0.w * th3);
        float q1 = fmaf(N1.x, th0, N1.y * th1) + fmaf(N1.z, th2, N1.w * th3);

        #pragma unroll
        for (int off = 16; off > 0; off >>= 1) {
            q0 += __shfl_xor_sync(0xffffffffu, q0, off);
            q1 += __shfl_xor_sync(0xffffffffu, q1, off);
        }

        // Ix_t (independent of h — hides under the reduction latency)
        float aix[4];
        #pragma unroll
        for (int c = 0; c < 4; c++) {
            float v =          Iw[c][0] * xA.x;
            v = fmaf(Iw[c][1], xA.y, v);
            v = fmaf(Iw[c][2], xA.z, v);
            v = fmaf(Iw[c][3], xA.w, v);
            v = fmaf(Iw[c][4], xB.x, v);
            v = fmaf(Iw[c][5], xB.y, v);
            v = fmaf(Iw[c][6], xB.z, v);
            v = fmaf(Iw[c][7], xB.w, v);
            aix[c] = ALPHA_F * v;
        }

        int par = t & 1;
        if (lane == 0) { sp[par][0][wid] = q0; sp[par][1][wid] = q1; }
        __syncthreads();
        float4 P0 = *(const float4*)&sp[par][0][0];
        float4 P1 = *(const float4*)&sp[par][1][0];
        float p0 = (P0.x + P0.y) + (P0.z + P0.w);
        float p1 = (P1.x + P1.y) + (P1.z + P1.w);

        h[0] = fmaf(0.9f, h[0], fmaf(K1_F, fmaf(M0.x, p0, M1.x * p1), aix[0]));
        h[1] = fmaf(0.9f, h[1], fmaf(K1_F, fmaf(M0.y, p0, M1.y * p1), aix[1]));
        h[2] = fmaf(0.9f, h[2], fmaf(K1_F, fmaf(M0.z, p0, M1.z * p1), aix[2]));
        h[3] = fmaf(0.9f, h[3], fmaf(K1_F, fmaf(M0.w, p0, M1.w * p1), aix[3]));

        // out channels 0,1: leaky scan of the rank coefficients (off h-critical-path)
        if (tid == 0) {
            oa  = fmaf(0.9f, oa,  K1_F * p0);
            obv = fmaf(0.9f, obv, K1_F * p1);
            ob01[(size_t)t * (OUTK / 2)] = make_float2(oa, obv);
        }

        xA = xAn; xB = xBn;
    }
}

// ---------------- launch ----------------
extern "C" void kernel_launch(void* const* d_in, const int* in_sizes, int n_in,
                              void* d_out, int out_size) {
    const float* x     = (const float*)d_in[0];   // (64,2048,8)
    const float* means = (const float*)d_in[1];   // (2,12)
    const float* L     = (const float*)d_in[2];   // (2,12,12)
    const float* mw    = (const float*)d_in[3];   // (2,)
    const float* seeds = (const float*)d_in[4];   // (4,512,12)
    const int*   cs    = (const int*)d_in[5];     // (64,)
    float* out = (float*)d_out;                   // (64,2048,10)

    setup_kernel<<<8, 256>>>(means, L, mw, seeds);
    xout_kernel<<<BATCH, 32>>>(x, out);
    rnn_kernel<<<BATCH, 128>>>(x, cs, out);
}

// round 6
// speedup vs baseline: 1.4938x; 1.0246x over previous
#include <cuda_runtime.h>
#include <cstdint>
#include <cstddef>

#define BATCH    64
#define SEQ      2048
#define INPUT    8
#define HIDDEN   512
#define NUM_SEEDS 4
#define DD       12
#define OUTK     10
#define ALPHA_F  0.1f
#define K1_F     (0.1f * (500.0f/512.0f))
#define QSCALE   4194304.0f          /* 2^22 fixed-point scale for warp reduction */
#define QINV     (1.0f/4194304.0f)

// ---------------- scratch (static __device__ — no allocation) ----------------
__device__ float g_m0[NUM_SEEDS][HIDDEN];
__device__ float g_m1[NUM_SEEDS][HIDDEN];
__device__ float g_n0[NUM_SEEDS][HIDDEN];
__device__ float g_n1[NUM_SEEDS][HIDDEN];
__device__ float g_I [NUM_SEEDS][HIDDEN][INPUT];

// native tanh (MUFU.TANH, sm_75+): 1 MUFU op, ~16cyc; rel err ~2^-11.
__device__ __forceinline__ float fast_tanh(float x) {
    float r;
    asm("tanh.approx.f32 %0, %1;" : "=f"(r) : "f"(x));
    return r;
}

// ---------------- kernel 1: combined mixture -> m, n, I ----------------
__global__ void setup_kernel(const float* __restrict__ means,
                             const float* __restrict__ L,
                             const float* __restrict__ mw,
                             const float* __restrict__ seeds) {
    __shared__ float Lc[DD][DD];
    __shared__ float mc[DD];
    int tid = threadIdx.x;

    float w0 = fmaxf(mw[0], 1e-6f);
    float w1 = fmaxf(mw[1], 1e-6f);
    float inv = 1.0f / (w0 + w1);
    w0 *= inv; w1 *= inv;

    if (tid < DD * DD) {
        int d = tid / DD, e = tid - d * DD;
        float a = L[d * DD + e];
        float c = L[DD * DD + d * DD + e];
        float v = 0.0f;
        if (e < d) {
            v = w0 * a + w1 * c;
        } else if (e == d) {
            v = w0 * (fabsf(a - 1e-12f) + 1e-12f)
              + w1 * (fabsf(c - 1e-12f) + 1e-12f);
        }
        Lc[d][e] = v;
    }
    if (tid < DD) mc[tid] = w0 * means[tid] + w1 * means[DD + tid];
    __syncthreads();

    int g = blockIdx.x * blockDim.x + tid;      // 0..2047 = s*512 + h
    int s = g >> 9, h = g & 511;

    float sd[DD];
    #pragma unroll
    for (int e = 0; e < DD; e++) sd[e] = seeds[(size_t)g * DD + e];

    float comb[DD];
    #pragma unroll
    for (int d = 0; d < DD; d++) {
        float v = mc[d];
        for (int e = 0; e <= d; e++) v = fmaf(Lc[d][e], sd[e], v);
        comb[d] = v;
    }
    g_m0[s][h] = comb[0];
    g_m1[s][h] = comb[1];
    g_n0[s][h] = comb[2];
    g_n1[s][h] = comb[3];
    #pragma unroll
    for (int i = 0; i < INPUT; i++) g_I[s][h][i] = comb[4 + i];
}

// ---------------- kernel 2: output channels 2..9 (x-only, via pinv@span == I) ----
// out_t[2+i] = 0.9*out_{t-1}[2+i] + 0.1*x_t[i].  Independent of the RNN.
__global__ __launch_bounds__(32) void xout_kernel(const float* __restrict__ x,
                                                  float* __restrict__ out) {
    const int b = blockIdx.x;
    const int lane = threadIdx.x;
    if (lane >= INPUT) return;

    const float* src = x + (size_t)b * SEQ * INPUT + lane;
    float* ob = out + (size_t)b * SEQ * OUTK + 2 + lane;

    float acc = 0.0f;
    #pragma unroll 8
    for (int t = 0; t < SEQ; t++) {
        acc = fmaf(0.9f, acc, ALPHA_F * src[(size_t)t * INPUT]);
        ob[(size_t)t * OUTK] = acc;
    }
}

// ---------------- kernel 3: the sequential RNN scan ----------------
// 1 block per batch, 128 threads, 4 hidden units per thread (contiguous).
// Per step: th=tanh(h); q_r = n_r . th in 2^22 fixed point -> one
// redux.sync.add.s32 per q (replaces the 5-round shuffle butterfly);
// cross-warp combine of int partials via smem; m prescaled by 2^-22 so
// no extra multiplies appear on the chain.
__global__ __launch_bounds__(128, 1) void rnn_kernel(const float* __restrict__ x,
                                                     const int* __restrict__ cur_seeds,
                                                     float* __restrict__ out) {
    const int b = blockIdx.x;
    const int tid = threadIdx.x;
    const int wid = tid >> 5, lane = tid & 31;
    const int s = cur_seeds[b];
    const int h0 = tid * 4;

    // m prescaled by 2^-22 (p arrives as fixed-point-int converted to float)
    float4 M0 = *(const float4*)&g_m0[s][h0];
    float4 M1 = *(const float4*)&g_m1[s][h0];
    M0.x *= QINV; M0.y *= QINV; M0.z *= QINV; M0.w *= QINV;
    M1.x *= QINV; M1.y *= QINV; M1.z *= QINV; M1.w *= QINV;
    // n prescaled by 2^22 so q-dot outputs are fixed-point ready
    float4 N0 = *(const float4*)&g_n0[s][h0];
    float4 N1 = *(const float4*)&g_n1[s][h0];
    N0.x *= QSCALE; N0.y *= QSCALE; N0.z *= QSCALE; N0.w *= QSCALE;
    N1.x *= QSCALE; N1.y *= QSCALE; N1.z *= QSCALE; N1.w *= QSCALE;

    float Iw[4][INPUT];
    #pragma unroll
    for (int c = 0; c < 4; c++) {
        float4 ia = *(const float4*)&g_I[s][h0 + c][0];
        float4 ib = *(const float4*)&g_I[s][h0 + c][4];
        Iw[c][0] = ia.x; Iw[c][1] = ia.y; Iw[c][2] = ia.z; Iw[c][3] = ia.w;
        Iw[c][4] = ib.x; Iw[c][5] = ib.y; Iw[c][6] = ib.z; Iw[c][7] = ib.w;
    }

    const float* xb = x + (size_t)b * SEQ * INPUT;
    float2* ob01 = (float2*)(out + (size_t)b * SEQ * OUTK);   // channels 0,1

    __shared__ __align__(16) int isp[2][2][4];   // [parity][r][warp] int partials

    float h[4] = {0.f, 0.f, 0.f, 0.f};
    float oa = 0.0f, obv = 0.0f;                  // out channel 0/1 scans (tid 0)
    const float K1S = K1_F * QINV;
    float4 xA = *(const float4*)(xb + 0);
    float4 xB = *(const float4*)(xb + 4);

    for (int t = 0; t < SEQ; t++) {
        // prefetch next x row (broadcast loads, off critical path)
        int tn = (t + 1 < SEQ) ? t + 1 : t;
        float4 xAn = *(const float4*)(xb + (size_t)tn * INPUT);
        float4 xBn = *(const float4*)(xb + (size_t)tn * INPUT + 4);

        float th0 = fast_tanh(h[0]);
        float th1 = fast_tanh(h[1]);
        float th2 = fast_tanh(h[2]);
        float th3 = fast_tanh(h[3]);

        float q0 = fmaf(N0.x, th0, N0.y * th1) + fmaf(N0.z, th2, N0.w * th3);
        float q1 = fmaf(N1.x, th0, N1.y * th1) + fmaf(N1.z, th2, N1.w * th3);

        // fixed-point warp reduction: one redux per q replaces 5 shuffle rounds
        int iq0 = __float2int_rn(q0);
        int iq1 = __float2int_rn(q1);
        iq0 = __reduce_add_sync(0xffffffffu, iq0);
        iq1 = __reduce_add_sync(0xffffffffu, iq1);

        // Ix_t (independent of h — issues under the reduction latency)
        float aix[4];
        #pragma unroll
        for (int c = 0; c < 4; c++) {
            float v =          Iw[c][0] * xA.x;
            v = fmaf(Iw[c][1], xA.y, v);
            v = fmaf(Iw[c][2], xA.z, v);
            v = fmaf(Iw[c][3], xA.w, v);
            v = fmaf(Iw[c][4], xB.x, v);
            v = fmaf(Iw[c][5], xB.y, v);
            v = fmaf(Iw[c][6], xB.z, v);
            v = fmaf(Iw[c][7], xB.w, v);
            aix[c] = ALPHA_F * v;
        }

        int par = t & 1;
        if (lane == 0) { isp[par][0][wid] = iq0; isp[par][1][wid] = iq1; }
        __syncthreads();
        int4 P0 = *(const int4*)&isp[par][0][0];
        int4 P1 = *(const int4*)&isp[par][1][0];
        int s0 = (P0.x + P0.y) + (P0.z + P0.w);    // exact int combine
        int s1 = (P1.x + P1.y) + (P1.z + P1.w);
        float p0 = (float)s0;                      // fixed-point, scale 2^22
        float p1 = (float)s1;

        h[0] = fmaf(0.9f, h[0], fmaf(K1_F, fmaf(M0.x, p0, M1.x * p1), aix[0]));
        h[1] = fmaf(0.9f, h[1], fmaf(K1_F, fmaf(M0.y, p0, M1.y * p1), aix[1]));
        h[2] = fmaf(0.9f, h[2], fmaf(K1_F, fmaf(M0.z, p0, M1.z * p1), aix[2]));
        h[3] = fmaf(0.9f, h[3], fmaf(K1_F, fmaf(M0.w, p0, M1.w * p1), aix[3]));

        // out channels 0,1: leaky scan of the rank coefficients (off h-critical-path)
        if (tid == 0) {
            oa  = fmaf(0.9f, oa,  K1S * p0);
            obv = fmaf(0.9f, obv, K1S * p1);
            ob01[(size_t)t * (OUTK / 2)] = make_float2(oa, obv);
        }

        xA = xAn; xB = xBn;
    }
}

// ---------------- launch ----------------
extern "C" void kernel_launch(void* const* d_in, const int* in_sizes, int n_in,
                              void* d_out, int out_size) {
    const float* x     = (const float*)d_in[0];   // (64,2048,8)
    const float* means = (const float*)d_in[1];   // (2,12)
    const float* L     = (const float*)d_in[2];   // (2,12,12)
    const float* mw    = (const float*)d_in[3];   // (2,)
    const float* seeds = (const float*)d_in[4];   // (4,512,12)
    const int*   cs    = (const int*)d_in[5];     // (64,)
    float* out = (float*)d_out;                   // (64,2048,10)

    setup_kernel<<<8, 256>>>(means, L, mw, seeds);
    xout_kernel<<<BATCH, 32>>>(x, out);
    rnn_kernel<<<BATCH, 128>>>(x, cs, out);
}